// round 8
// baseline (speedup 1.0000x reference)
#include <cuda_runtime.h>
#include <cuda_fp16.h>
#include <cstdint>

// ---------------------------------------------------------------------------
// Round-5 proven pipeline (f16 2:4 sparse splines + dense fp16 silu) plus a
// bounded int8 mma.sp probe: feature 0's spline term runs through s8 k64
// sparse with layout hypothesis Z. Wrong layout costs <=3.3e-4 extra error.
// ---------------------------------------------------------------------------

#define M_ROWS 4096
#define N_COLS 1024
#define BM 128
#define BN 256
#define NSP 128
#define NDN 16
#define NTOT (NSP + NDN)

__device__ __align__(16) __half   g_A [(size_t)M_ROWS * 4096];  // f16 comp A
__device__ __align__(16) __half   g_As[(size_t)M_ROWS * 1024];  // silu
__device__ __align__(16) __half   g_B [(size_t)N_COLS * 8192];  // f16 spline B
__device__ __align__(16) __half   g_Bb[(size_t)N_COLS * 1024];  // base W
__device__ __align__(16) uint32_t g_M [(size_t)M_ROWS * 256];   // f16 meta
// probe (feature 0 only)
__device__ __align__(16) uint8_t  g_A8[(size_t)M_ROWS * 4];
__device__ uint32_t g_M8[M_ROWS];
__device__ __align__(8) uint8_t   g_B8[(size_t)N_COLS * 8];
__device__ float g_sc8[N_COLS];

__device__ __forceinline__ uint32_t smem_u32(const void* p) {
    uint32_t a;
    asm("{ .reg .u64 t; cvta.to.shared.u64 t, %1; cvt.u32.u64 %0, t; }"
        : "=r"(a) : "l"(p));
    return a;
}
__device__ __forceinline__ void cp_async16(uint32_t s, const void* g) {
    asm volatile("cp.async.cg.shared.global [%0], [%1], 16;" :: "r"(s), "l"(g));
}
__device__ __forceinline__ void cp_async8(uint32_t s, const void* g) {
    asm volatile("cp.async.ca.shared.global [%0], [%1], 8;" :: "r"(s), "l"(g));
}
__device__ __forceinline__ void ldmatrix_x4(uint32_t* r, uint32_t addr) {
    asm volatile("ldmatrix.sync.aligned.m8n8.x4.shared.b16 {%0,%1,%2,%3}, [%4];"
                 : "=r"(r[0]), "=r"(r[1]), "=r"(r[2]), "=r"(r[3]) : "r"(addr));
}
__device__ __forceinline__ void mma_sp_f16(float* d, const uint32_t* a,
                                           const uint32_t* b, uint32_t e) {
    asm volatile(
        "mma.sp::ordered_metadata.sync.aligned.m16n8k32.row.col.f32.f16.f16.f32 "
        "{%0,%1,%2,%3}, {%4,%5,%6,%7}, {%8,%9,%10,%11}, {%0,%1,%2,%3}, %12, 0x0;"
        : "+f"(d[0]), "+f"(d[1]), "+f"(d[2]), "+f"(d[3])
        : "r"(a[0]), "r"(a[1]), "r"(a[2]), "r"(a[3]),
          "r"(b[0]), "r"(b[1]), "r"(b[2]), "r"(b[3]), "r"(e));
}
__device__ __forceinline__ void mma_sp_s8(int* d, const uint32_t* a,
                                          const uint32_t* b, uint32_t e) {
    asm volatile(
        "mma.sp::ordered_metadata.sync.aligned.m16n8k64.row.col.s32.s8.s8.s32 "
        "{%0,%1,%2,%3}, {%4,%5,%6,%7}, {%8,%9,%10,%11}, {%0,%1,%2,%3}, %12, 0x0;"
        : "+r"(d[0]), "+r"(d[1]), "+r"(d[2]), "+r"(d[3])
        : "r"(a[0]), "r"(a[1]), "r"(a[2]), "r"(a[3]),
          "r"(b[0]), "r"(b[1]), "r"(b[2]), "r"(b[3]), "r"(e));
}
__device__ __forceinline__ void mma16816(float* d, const uint32_t* a,
                                         const uint32_t* b) {
    asm volatile(
        "mma.sync.aligned.m16n8k16.row.col.f32.f16.f16.f32 "
        "{%0,%1,%2,%3}, {%4,%5,%6,%7}, {%8,%9}, {%0,%1,%2,%3};"
        : "+f"(d[0]), "+f"(d[1]), "+f"(d[2]), "+f"(d[3])
        : "r"(a[0]), "r"(a[1]), "r"(a[2]), "r"(a[3]), "r"(b[0]), "r"(b[1]));
}

// ---------------------------------------------------------------------------
__global__ void build_A_kernel(const float* __restrict__ x) {
    __shared__ unsigned char nib[512];
    const int t  = threadIdx.x;
    const int b  = blockIdx.x >> 2;
    const int i0 = (blockIdx.x & 3) << 8;

    float xv = x[b * 1024 + i0 + t];
    g_As[(size_t)b * 1024 + i0 + t] = __float2half(xv / (1.0f + __expf(-xv)));

    int j = (int)floorf((xv + 2.2f) * 2.5f);
    bool ok = (j >= 0) && (j <= 10);
    float tj = (float)(j - 3) * 0.4f - 1.0f;
    float u  = (xv - tj) * 2.5f;
    float um = 1.0f - u;
    float u2 = u * u, u3 = u2 * u;
    float W0 = um * um * um * (1.0f / 6.0f);
    float W1 = (3.0f * u3 - 6.0f * u2 + 4.0f) * (1.0f / 6.0f);
    float W2 = (-3.0f * u3 + 3.0f * u2 + 3.0f * u + 1.0f) * (1.0f / 6.0f);
    float W3 = u3 * (1.0f / 6.0f);
    if (!ok) { W0 = W1 = W2 = W3 = 0.0f; }

    int   qe  = (j + 1) & 1;
    int   pe  = j - 3 + qe;
    float We0 = qe ? W1 : W0, We1 = qe ? W3 : W2;
    int   e0  = max(min(pe >> 1, 2), 0), e1 = e0 + 1;
    float ve0 = (2 * e0 == pe) ? We0 : ((2 * e0 == pe + 2) ? We1 : 0.0f);
    float ve1 = (2 * e1 == pe) ? We0 : ((2 * e1 == pe + 2) ? We1 : 0.0f);
    int   qo  = qe ^ 1;
    int   po  = j - 3 + qo;
    float Wo0 = qo ? W1 : W0, Wo1 = qo ? W3 : W2;
    int   o0  = max(min(po >> 1, 2), 0), o1 = o0 + 1;
    float vo0 = (2 * o0 + 1 == po) ? Wo0 : ((2 * o0 + 1 == po + 2) ? Wo1 : 0.0f);
    float vo1 = (2 * o1 + 1 == po) ? Wo0 : ((2 * o1 + 1 == po + 2) ? Wo1 : 0.0f);

    __half2 hv[2];
    hv[0] = __floats2half2_rn(ve0, ve1);
    hv[1] = __floats2half2_rn(vo0, vo1);
    *(uint2*)(g_A + (size_t)b * 4096 + (size_t)(i0 + t) * 4) = *(uint2*)hv;

    nib[2 * t]     = (unsigned char)(e0 | (e1 << 2));
    nib[2 * t + 1] = (unsigned char)(o0 | (o1 << 2));

    if (i0 == 0 && t == 0) {   // probe data for feature 0
        uint32_t q0 = (uint32_t)(uint8_t)(int8_t)__float2int_rn(ve0 * 190.0f);
        uint32_t q1 = (uint32_t)(uint8_t)(int8_t)__float2int_rn(ve1 * 190.0f);
        uint32_t q2 = (uint32_t)(uint8_t)(int8_t)__float2int_rn(vo0 * 190.0f);
        uint32_t q3 = (uint32_t)(uint8_t)(int8_t)__float2int_rn(vo1 * 190.0f);
        *(uint32_t*)(g_A8 + (size_t)b * 4) = q0 | (q1 << 8) | (q2 << 16) | (q3 << 24);
        g_M8[b] = 0x44444400u | (uint32_t)(e0 | (e1 << 2))
                              | ((uint32_t)(o0 | (o1 << 2)) << 4);
    }
    __syncthreads();

    if (t < 64) {
        uint32_t w = 0;
#pragma unroll
        for (int q = 0; q < 8; q++) w |= (uint32_t)nib[8 * t + q] << (4 * q);
        g_M[(size_t)b * 256 + (blockIdx.x & 3) * 64 + t] = w;
    }
}

// ---------------------------------------------------------------------------
__global__ void pack_W_kernel(const float* __restrict__ bw,
                              const float* __restrict__ sw,
                              const float* __restrict__ ss) {
    const int t  = threadIdx.x;
    const int o  = blockIdx.x >> 2;
    const int i0 = (blockIdx.x & 3) << 8;
    const int e  = o * 1024 + i0 + t;

    float sc = ss[e];
    const float* swp = sw + (size_t)e * 8;
    g_Bb[e] = __float2half(bw[e]);

    __half2 h[4];
    if (i0 + t == 0) {   // feature 0 handled by s8 probe
        h[0] = h[1] = h[2] = h[3] = __floats2half2_rn(0.0f, 0.0f);
    } else {
        h[0] = __floats2half2_rn(swp[0] * sc, swp[2] * sc);
        h[1] = __floats2half2_rn(swp[4] * sc, swp[6] * sc);
        h[2] = __floats2half2_rn(swp[1] * sc, swp[3] * sc);
        h[3] = __floats2half2_rn(swp[5] * sc, swp[7] * sc);
    }
    *(uint4*)(g_B + (size_t)o * 8192 + (size_t)(i0 + t) * 8) = *(uint4*)h;

    if (i0 == 0 && t == 0) {   // probe weights: feature 0, per-o scale
        float m = 1e-20f;
#pragma unroll
        for (int k = 0; k < 8; k++) m = fmaxf(m, fabsf(swp[k] * sc));
        float inv = 127.0f / m;
        g_sc8[o] = m / (127.0f * 190.0f);
        uint32_t lo = 0, hi = 0;
#pragma unroll
        for (int k = 0; k < 4; k++) {
            lo |= ((uint32_t)(uint8_t)(int8_t)__float2int_rn(swp[2 * k] * sc * inv)) << (8 * k);
            hi |= ((uint32_t)(uint8_t)(int8_t)__float2int_rn(swp[2 * k + 1] * sc * inv)) << (8 * k);
        }
        *(uint2*)(g_B8 + (size_t)o * 8) = make_uint2(lo, hi);
    }
}

// ---------------------------------------------------------------------------
// Main GEMM: exact round-5 structure (f16 sparse + dense silu).
// ---------------------------------------------------------------------------
#define STG_A (128 * 144)
#define STG_B (256 * 144)
#define STG_M 1024
#define STG   (STG_A + STG_B + STG_M)
#define SMEM_TOT (3 * STG)

__global__ void __launch_bounds__(256, 1)
gemm_kernel(float* __restrict__ C) {
    extern __shared__ char smc[];
    const uint32_t sb = smem_u32(smc);
    const int tid  = threadIdx.x;
    const int wid  = tid >> 5;
    const int lane = tid & 31;
    const int wm   = (wid >> 2) * 64;
    const int wn   = (wid & 3) * 64;
    const int mBase = blockIdx.y * BM;
    const int nBase = blockIdx.x * BN;

    float acc[4][8][4];
#pragma unroll
    for (int mb = 0; mb < 4; mb++)
#pragma unroll
        for (int nb = 0; nb < 8; nb++)
#pragma unroll
            for (int r = 0; r < 4; r++) acc[mb][nb][r] = 0.0f;

#define PRE(buf, it)                                                           \
    do {                                                                       \
        uint32_t d0 = sb + (buf) * STG;                                        \
        if ((it) < NSP) {                                                      \
            _Pragma("unroll")                                                  \
            for (int u = 0; u < 2; u++) {                                      \
                int f = tid + u * 256, r = f >> 2, q = f & 3;                  \
                cp_async16(d0 + r * 144 + q * 16,                              \
                    (const char*)g_A + (size_t)(mBase + r) * 8192 +            \
                    (it) * 64 + q * 16);                                       \
            }                                                                  \
            _Pragma("unroll")                                                  \
            for (int u = 0; u < 8; u++) {                                      \
                int f = tid + u * 256, r = f >> 3, q = f & 7;                  \
                cp_async16(d0 + STG_A + r * 144 + q * 16,                      \
                    (const char*)g_B + (size_t)(nBase + r) * 16384 +           \
                    (it) * 128 + q * 16);                                      \
            }                                                                  \
            if (tid < 128)                                                     \
                cp_async8(d0 + STG_A + STG_B + tid * 8,                        \
                    (const char*)g_M + (size_t)(mBase + tid) * 1024 +          \
                    (it) * 8);                                                 \
        } else {                                                               \
            int itd = (it) - NSP;                                              \
            _Pragma("unroll")                                                  \
            for (int u = 0; u < 4; u++) {                                      \
                int f = tid + u * 256, r = f >> 3, q = f & 7;                  \
                cp_async16(d0 + r * 144 + q * 16,                              \
                    (const char*)g_As + (size_t)(mBase + r) * 2048 +           \
                    itd * 128 + q * 16);                                       \
            }                                                                  \
            _Pragma("unroll")                                                  \
            for (int u = 0; u < 8; u++) {                                      \
                int f = tid + u * 256, r = f >> 3, q = f & 7;                  \
                cp_async16(d0 + STG_A + r * 144 + q * 16,                      \
                    (const char*)g_Bb + (size_t)(nBase + r) * 2048 +           \
                    itd * 128 + q * 16);                                       \
            }                                                                  \
        }                                                                      \
        asm volatile("cp.async.commit_group;" ::: "memory");                   \
    } while (0)

    PRE(0, 0);
    PRE(1, 1);

    for (int it = 0; it < NTOT; it++) {
        const int buf = it % 3;
        if (it + 2 < NTOT) {
            PRE((it + 2) % 3, it + 2);
            asm volatile("cp.async.wait_group 2;" ::: "memory");
        } else {
            asm volatile("cp.async.wait_group 0;" ::: "memory");
        }
        __syncthreads();

        const uint32_t aB = sb + buf * STG;
        const uint32_t bB = aB + STG_A;

        if (it < NSP) {
            const char* mB = smc + buf * STG + STG_A + STG_B;
#pragma unroll
            for (int c = 0; c < 2; c++) {
                uint32_t me[4];
#pragma unroll
                for (int mb = 0; mb < 4; mb++) {
                    int r0 = wm + mb * 16 + (lane >> 2);
                    uint32_t w0 = *(const uint32_t*)(mB + r0 * 8 + c * 4);
                    uint32_t w1 = *(const uint32_t*)(mB + (r0 + 8) * 8 + c * 4);
                    me[mb] = (lane & 1) ? ((w0 >> 16) | (w1 & 0xFFFF0000u))
                                        : ((w0 & 0xFFFFu) | (w1 << 16));
                }
                uint32_t a[4][4];
#pragma unroll
                for (int mb = 0; mb < 4; mb++)
                    ldmatrix_x4(a[mb], aB + (wm + mb * 16 + (lane & 15)) * 144
                                          + c * 32 + ((lane >> 4) << 4));
                uint32_t bq[8][4];
#pragma unroll
                for (int nb = 0; nb < 8; nb++)
                    ldmatrix_x4(bq[nb], bB + (wn + nb * 8 + (lane & 7)) * 144
                                           + c * 64 + ((lane >> 3) << 4));
#pragma unroll
                for (int mb = 0; mb < 4; mb++)
#pragma unroll
                    for (int nb = 0; nb < 8; nb++)
                        mma_sp_f16(acc[mb][nb], a[mb], bq[nb], me[mb]);
            }
        } else {
#pragma unroll
            for (int ks = 0; ks < 4; ks++) {
                uint32_t a[4][4], bf[8][2];
#pragma unroll
                for (int mb = 0; mb < 4; mb++)
                    ldmatrix_x4(a[mb], aB + (wm + mb * 16 + (lane & 15)) * 144
                                          + ks * 32 + ((lane >> 4) << 4));
#pragma unroll
                for (int np = 0; np < 4; np++) {
                    uint32_t q[4];
                    ldmatrix_x4(q, bB + (wn + np * 16 + (lane & 7)
                                         + ((lane >> 4) << 3)) * 144
                                      + ks * 32 + (((lane >> 3) & 1) << 4));
                    bf[np * 2][0] = q[0]; bf[np * 2][1] = q[1];
                    bf[np * 2 + 1][0] = q[2]; bf[np * 2 + 1][1] = q[3];
                }
#pragma unroll
                for (int mb = 0; mb < 4; mb++)
#pragma unroll
                    for (int nb = 0; nb < 8; nb++)
                        mma16816(acc[mb][nb], a[mb], bf[nb]);
            }
        }
        __syncthreads();
    }

    const int gr = lane >> 2;
    const int tc = lane & 3;
#pragma unroll
    for (int mb = 0; mb < 4; mb++) {
#pragma unroll
        for (int nb = 0; nb < 8; nb++) {
            int row = mBase + wm + mb * 16 + gr;
            int col = nBase + wn + nb * 8 + tc * 2;
            *(float2*)&C[(size_t)row * N_COLS + col] =
                make_float2(acc[mb][nb][0], acc[mb][nb][1]);
            *(float2*)&C[(size_t)(row + 8) * N_COLS + col] =
                make_float2(acc[mb][nb][2], acc[mb][nb][3]);
        }
    }
}

// ---------------------------------------------------------------------------
// Probe: feature-0 spline term via s8 k64 mma.sp, layout Z, explicit frags.
// A frag: a0=row gid kc[4t4..], a1=row gid+8 (only t4==0 nonzero here).
// B frag: b0=col gid k[4t4..] (t4<2 nonzero). Meta Z: T0/T1 = word0 of rows
// gid/gid+8; T2/T3 = word1 (zeros -> 0x44444444 pad).
// ---------------------------------------------------------------------------
__global__ void __launch_bounds__(256)
probe_kernel(float* __restrict__ C) {
    const int tid = threadIdx.x, w = tid >> 5, lane = tid & 31;
    const int t4 = lane & 3, gid = lane >> 2;
    const int r0 = blockIdx.y * 128 + w * 16;
    const int nBase = blockIdx.x * 128;

    uint32_t a[4] = {0, 0, 0, 0};
    uint32_t me = 0x44444444u;
    if (t4 == 0) {
        a[0] = *(const uint32_t*)(g_A8 + (size_t)(r0 + gid) * 4);
        a[1] = *(const uint32_t*)(g_A8 + (size_t)(r0 + gid + 8) * 4);
        me = g_M8[r0 + gid];
    } else if (t4 == 1) {
        me = g_M8[r0 + gid + 8];
    }

#pragma unroll 4
    for (int nt = 0; nt < 16; nt++) {
        int c0 = nBase + nt * 8;
        uint32_t b[4] = {0, 0, 0, 0};
        if (t4 < 2) b[0] = *(const uint32_t*)(g_B8 + (size_t)(c0 + gid) * 8 + 4 * t4);
        int acc[4] = {0, 0, 0, 0};
        mma_sp_s8(acc, a, b, me);
        int col = c0 + 2 * t4;
        float s0 = g_sc8[col], s1 = g_sc8[col + 1];
        float* p0 = &C[(size_t)(r0 + gid) * N_COLS + col];
        float* p1 = &C[(size_t)(r0 + gid + 8) * N_COLS + col];
        p0[0] += acc[0] * s0; p0[1] += acc[1] * s1;
        p1[0] += acc[2] * s0; p1[1] += acc[3] * s1;
    }
}

// ---------------------------------------------------------------------------
extern "C" void kernel_launch(void* const* d_in, const int* in_sizes, int n_in,
                              void* d_out, int out_size) {
    const float* x  = (const float*)d_in[0];
    const float* bw = (const float*)d_in[1];
    const float* sw = (const float*)d_in[2];
    const float* ss = (const float*)d_in[3];
    float* out = (float*)d_out;

    build_A_kernel<<<(M_ROWS * 1024) / 256, 256>>>(x);
    pack_W_kernel<<<(N_COLS * 1024) / 256, 256>>>(bw, sw, ss);

    cudaFuncSetAttribute(gemm_kernel,
                         cudaFuncAttributeMaxDynamicSharedMemorySize, SMEM_TOT);
    gemm_kernel<<<dim3(N_COLS / BN, M_ROWS / BM), 256, SMEM_TOT>>>(out);
    probe_kernel<<<dim3(N_COLS / 128, M_ROWS / 128), 256>>>(out);
}